// round 15
// baseline (speedup 1.0000x reference)
#include <cuda_runtime.h>
#include <cuda_fp16.h>
#include <math.h>

#define BB 4
#define CC 128
#define HH 128
#define WW 240
#define EE 64
#define RNG 4
#define KK 9          // 2*RNG+1
#define HW (HH*WW)    // 30720
#define EPSN 1e-6f

// Normalized embeddings, fp16, [tensor][b][q][e], e contiguous. 31.5 MB.
__device__ __align__(16) __half g_emb[2][(size_t)BB * HW * EE];

// phi tf32 fragments: [kt(16)][nt(8)][lane(32)] -> uint4 (b0_hi,b1_hi,b0_lo,b1_lo).
__device__ uint4 g_phi_frag[16 * 8 * 32];

// ---------------------------------------------------------------------------
__device__ __forceinline__ void mma_tf32(float& d0, float& d1, float& d2, float& d3,
                                         unsigned a0, unsigned a1, unsigned a2, unsigned a3,
                                         unsigned b0, unsigned b1)
{
    asm volatile(
        "mma.sync.aligned.m16n8k8.row.col.f32.tf32.tf32.f32 "
        "{%0,%1,%2,%3}, {%4,%5,%6,%7}, {%8,%9}, {%0,%1,%2,%3};\n"
        : "+f"(d0), "+f"(d1), "+f"(d2), "+f"(d3)
        : "r"(a0), "r"(a1), "r"(a2), "r"(a3), "r"(b0), "r"(b1));
}

__device__ __forceinline__ unsigned cvt_tf32_rna(float x)
{
    unsigned r;
    asm("cvt.rna.tf32.f32 %0, %1;" : "=r"(r) : "f"(x));
    return r;
}

__device__ __forceinline__ unsigned round_tf32_bits(float x)
{
    unsigned u = __float_as_uint(x);
    return (u + 0x1000u) & 0xFFFFE000u;
}

__device__ __forceinline__ float2 h2f(unsigned u)
{
    __half2 h = *reinterpret_cast<__half2*>(&u);
    return __half22float2(h);
}

// ---- cp.async helpers -----------------------------------------------------
__device__ __forceinline__ void cp_async16(unsigned dst_smem, const void* src)
{
    asm volatile("cp.async.cg.shared.global [%0], [%1], 16;"
                 :: "r"(dst_smem), "l"(src));
}
__device__ __forceinline__ void cp_commit()
{
    asm volatile("cp.async.commit_group;");
}
template<int N>
__device__ __forceinline__ void cp_wait()
{
    asm volatile("cp.async.wait_group %0;" :: "n"(N));
}

// ---------------------------------------------------------------------------
// prep_phi: tf32 hi/lo B fragments.
// ---------------------------------------------------------------------------
__global__ void prep_phi_kernel(const float* __restrict__ phi)
{
    const int idx = blockIdx.x * blockDim.x + threadIdx.x;   // 0..4095
    if (idx >= 16 * 8 * 32) return;
    const int lane = idx & 31;
    const int nt   = (idx >> 5) & 7;
    const int kt   = idx >> 8;

    const int e  = nt * 8 + (lane >> 2);
    const int c0 = kt * 8 + (lane & 3);

    const float x0 = phi[e * CC + c0];
    const float x1 = phi[e * CC + c0 + 4];

    const unsigned h0 = cvt_tf32_rna(x0);
    const unsigned h1 = cvt_tf32_rna(x1);

    uint4 v;
    v.x = h0;
    v.y = h1;
    v.z = __float_as_uint(x0 - __uint_as_float(h0));
    v.w = __float_as_uint(x1 - __uint_as_float(h1));
    g_phi_frag[idx] = v;
}

// ---------------------------------------------------------------------------
// embed (round-11 best, unchanged): CH=32 double-buffer cp.async pipeline,
// tf32 MMA 2-product, coalesced fp16 epilogue via smem staging. 4 blocks/SM.
// ---------------------------------------------------------------------------
#define QT 128
#define S_A 136                   // floats per channel row (128 + 8 pad)
#define CH 32                     // channels per pipeline chunk
#define NCHUNK (CC / CH)          // 4
#define OS 72                     // output stage stride in halves

__global__ __launch_bounds__(128, 4)
void embed_kernel(const float* __restrict__ FL,
                  const float* __restrict__ FR)
{
    extern __shared__ __align__(16) float A_s[];   // [2][CH][S_A] = 34816 B

    const int t      = threadIdx.x;
    const int qbase  = blockIdx.x * QT;
    const int b      = blockIdx.y;
    const int tensor = blockIdx.z;

    const float* __restrict__ F =
        (tensor == 0 ? FL : FR) + (size_t)b * CC * HW;

    const int warp = t >> 5;
    const int lane = t & 31;
    const int g    = lane >> 2;
    const int tg   = lane & 3;

    const int tq_c = t & 31;
    #define ISSUE_CHUNK(ch, buf)                                              \
    {                                                                         \
        float* __restrict__ dstb = A_s + (buf) * (CH * S_A);                  \
        _Pragma("unroll")                                                     \
        for (int i = 0; i < 8; i++) {                                         \
            const int cl = i * 4 + warp;                                      \
            const float* src = &F[(size_t)((ch) * CH + cl) * HW + qbase + tq_c * 4]; \
            const unsigned dst = (unsigned)__cvta_generic_to_shared(          \
                &dstb[cl * S_A + tq_c * 4]);                                  \
            cp_async16(dst, src);                                             \
        }                                                                     \
        cp_commit();                                                          \
    }

    float acc[2][8][4];
#pragma unroll
    for (int mt = 0; mt < 2; mt++)
#pragma unroll
        for (int nt = 0; nt < 8; nt++)
#pragma unroll
            for (int i = 0; i < 4; i++) acc[mt][nt][i] = 0.0f;

    const uint4* __restrict__ Bf = g_phi_frag + lane;
    const int r0 = (warp * 2) * 16 + g;       // mt=0 output row (0..127)
    const int r2 = (warp * 2 + 1) * 16 + g;   // mt=1

    ISSUE_CHUNK(0, 0);

#pragma unroll
    for (int ch = 0; ch < NCHUNK; ch++) {
        if (ch + 1 < NCHUNK) {
            ISSUE_CHUNK(ch + 1, (ch + 1) & 1);
            cp_wait<1>();
        } else {
            cp_wait<0>();
        }
        __syncthreads();

        const float* __restrict__ buf = A_s + (ch & 1) * (CH * S_A);
#pragma unroll
        for (int ktl = 0; ktl < CH / 8; ktl++) {          // 4 k-tiles per chunk
            const int cl0 = ktl * 8 + tg;
            unsigned a[2][4];
            a[0][0] = round_tf32_bits(buf[cl0 * S_A + r0]);
            a[0][1] = round_tf32_bits(buf[cl0 * S_A + r0 + 8]);
            a[0][2] = round_tf32_bits(buf[(cl0 + 4) * S_A + r0]);
            a[0][3] = round_tf32_bits(buf[(cl0 + 4) * S_A + r0 + 8]);
            a[1][0] = round_tf32_bits(buf[cl0 * S_A + r2]);
            a[1][1] = round_tf32_bits(buf[cl0 * S_A + r2 + 8]);
            a[1][2] = round_tf32_bits(buf[(cl0 + 4) * S_A + r2]);
            a[1][3] = round_tf32_bits(buf[(cl0 + 4) * S_A + r2 + 8]);

            const int kt = ch * (CH / 8) + ktl;
#pragma unroll
            for (int nt = 0; nt < 8; nt++) {
                const uint4 bf = Bf[(kt * 8 + nt) * 32];
#pragma unroll
                for (int mt = 0; mt < 2; mt++) {
                    mma_tf32(acc[mt][nt][0], acc[mt][nt][1], acc[mt][nt][2], acc[mt][nt][3],
                             a[mt][0], a[mt][1], a[mt][2], a[mt][3], bf.x, bf.y);
                    mma_tf32(acc[mt][nt][0], acc[mt][nt][1], acc[mt][nt][2], acc[mt][nt][3],
                             a[mt][0], a[mt][1], a[mt][2], a[mt][3], bf.z, bf.w);
                }
            }
        }
        __syncthreads();
    }
    #undef ISSUE_CHUNK

    // ---- Normalize + stage to smem (reuse A_s; [QT][OS] halves = 18 KB) ----
    __half* __restrict__ stage = reinterpret_cast<__half*>(A_s);
#pragma unroll
    for (int mt = 0; mt < 2; mt++) {
        const int r = (mt == 0 ? r0 : r2);
        float s0 = 0.0f, s1 = 0.0f;
#pragma unroll
        for (int nt = 0; nt < 8; nt++) {
            s0 = fmaf(acc[mt][nt][0], acc[mt][nt][0], s0);
            s0 = fmaf(acc[mt][nt][1], acc[mt][nt][1], s0);
            s1 = fmaf(acc[mt][nt][2], acc[mt][nt][2], s1);
            s1 = fmaf(acc[mt][nt][3], acc[mt][nt][3], s1);
        }
        s0 += __shfl_xor_sync(0xffffffffu, s0, 1);
        s0 += __shfl_xor_sync(0xffffffffu, s0, 2);
        s1 += __shfl_xor_sync(0xffffffffu, s1, 1);
        s1 += __shfl_xor_sync(0xffffffffu, s1, 2);
        const float inv0 = 1.0f / (sqrtf(s0) + EPSN);
        const float inv1 = 1.0f / (sqrtf(s1) + EPSN);

#pragma unroll
        for (int nt = 0; nt < 8; nt++) {
            const int e = nt * 8 + 2 * tg;
            *reinterpret_cast<__half2*>(&stage[r * OS + e]) =
                __floats2half2_rn(acc[mt][nt][0] * inv0, acc[mt][nt][1] * inv0);
            *reinterpret_cast<__half2*>(&stage[(r + 8) * OS + e]) =
                __floats2half2_rn(acc[mt][nt][2] * inv1, acc[mt][nt][3] * inv1);
        }
    }
    __syncthreads();

    // ---- Copy stage -> global, fully coalesced (8 uint4/thread) ----
    __half* __restrict__ outT = g_emb[tensor] + ((size_t)b * HW + qbase) * EE;
#pragma unroll
    for (int i = 0; i < 8; i++) {
        const int idx = i * 128 + t;       // 0..1023
        const int row = idx >> 3;
        const int col = idx & 7;
        const uint4 v = *reinterpret_cast<const uint4*>(&stage[row * OS + col * 8]);
        reinterpret_cast<uint4*>(&outT[(size_t)row * EE])[col] = v;
    }
}

// ---------------------------------------------------------------------------
// corr: one block per (b,h) row (round-11 structure). FR row staged in smem
// as FP32 (convert once at stage time -> kills 80 F2F cvts per thread-iter).
// 8-lane groups, shared-frac factorization.
// ---------------------------------------------------------------------------
__global__ __launch_bounds__(256)
void corr_kernel(const float* __restrict__ d0,
                 float* __restrict__ out)
{
    extern __shared__ __align__(16) float FRF_s[];   // [240][64] fp32 = 61440 B

    const int h = blockIdx.x;
    const int b = blockIdx.y;
    const int t = threadIdx.x;

    const __half* __restrict__ fl_row =
        &g_emb[0][((size_t)b * HW + (size_t)h * WW) * EE];
    const __half* __restrict__ fr_row =
        &g_emb[1][((size_t)b * HW + (size_t)h * WW) * EE];
    const float* __restrict__ d_row = d0 + (size_t)b * HW + (size_t)h * WW;

    // Stage FR row as fp32: 1920 uint4 in -> 3840 float4 out, 7.5/thread.
    {
        const uint4* __restrict__ src = reinterpret_cast<const uint4*>(fr_row);
#pragma unroll
        for (int i = 0; i < 8; i++) {
            const int idx = i * 256 + t;          // uint4 index 0..1919
            if (idx < 1920) {
                const uint4 v = __ldg(src + idx);
                const float2 a0 = h2f(v.x);
                const float2 a1 = h2f(v.y);
                const float2 a2 = h2f(v.z);
                const float2 a3 = h2f(v.w);
                float4 f0, f1;
                f0.x = a0.x; f0.y = a0.y; f0.z = a1.x; f0.w = a1.y;
                f1.x = a2.x; f1.y = a2.y; f1.z = a3.x; f1.w = a3.y;
                float4* dst = reinterpret_cast<float4*>(&FRF_s[idx * 8]);
                dst[0] = f0;
                dst[1] = f1;
            }
        }
    }
    __syncthreads();

    const int gid = t >> 3;        // 32 groups of 8 lanes
    const int sub = t & 7;

#pragma unroll 1
    for (int it = 0; it < 8; it++) {
        const int w = gid + 32 * it;
        const bool active = (w < WW);
        const int wc = active ? w : (WW - 1);

        const uint4 flv =
            __ldg(reinterpret_cast<const uint4*>(&fl_row[(size_t)wc * EE]) + sub);
        const float2 fl0 = h2f(flv.x);
        const float2 fl1 = h2f(flv.y);
        const float2 fl2 = h2f(flv.z);
        const float2 fl3 = h2f(flv.w);

        const float d = __ldg(&d_row[wc]);
        const float xf   = (float)wc - d;
        const float f0f  = floorf(xf);
        const float frac = xf - f0f;
        const int base   = (int)f0f - RNG;

        float s[10];
#pragma unroll
        for (int j = 0; j < 10; j++) {
            const int idx = min(max(base + j, 0), WW - 1);
            const float4* __restrict__ fr4 =
                reinterpret_cast<const float4*>(&FRF_s[idx * EE + sub * 8]);
            const float4 fa = fr4[0];
            const float4 fb = fr4[1];
            float dot;
            dot = fl0.x * fa.x;
            dot = fmaf(fl0.y, fa.y, dot);
            dot = fmaf(fl1.x, fa.z, dot);
            dot = fmaf(fl1.y, fa.w, dot);
            dot = fmaf(fl2.x, fb.x, dot);
            dot = fmaf(fl2.y, fb.y, dot);
            dot = fmaf(fl3.x, fb.z, dot);
            dot = fmaf(fl3.y, fb.w, dot);
            s[j] = dot;
        }

#pragma unroll
        for (int j = 0; j < 10; j++) {
            float p = s[j];
            p += __shfl_xor_sync(0xffffffffu, p, 4);
            p += __shfl_xor_sync(0xffffffffu, p, 2);
            p += __shfl_xor_sync(0xffffffffu, p, 1);
            s[j] = p;
        }

        float sA = s[8], sB = s[9];
#pragma unroll
        for (int k = 1; k < 8; k++)
            if (sub == k) { sA = s[8 - k]; sB = s[9 - k]; }

        if (active) {
            const float omf = 1.0f - frac;
            out[(((size_t)b * KK + sub) * HH + h) * WW + w] = sA * omf + sB * frac;
            if (sub == 0)
                out[(((size_t)b * KK + 8) * HH + h) * WW + w] = s[0] * omf + s[1] * frac;
        }
    }
}

extern "C" void kernel_launch(void* const* d_in, const int* in_sizes, int n_in,
                              void* d_out, int out_size)
{
    const float* F_L   = (const float*)d_in[0];
    const float* F_R   = (const float*)d_in[1];
    const float* d0    = (const float*)d_in[2];
    const float* phi_w = (const float*)d_in[3];
    float* out = (float*)d_out;

    const int embed_smem = 2 * CH * S_A * (int)sizeof(float);   // 34816 B
    const int corr_smem  = WW * EE * (int)sizeof(float);        // 61440 B
    cudaFuncSetAttribute(embed_kernel,
                         cudaFuncAttributeMaxDynamicSharedMemorySize, embed_smem);
    cudaFuncSetAttribute(corr_kernel,
                         cudaFuncAttributeMaxDynamicSharedMemorySize, corr_smem);

    prep_phi_kernel<<<16, 256>>>(phi_w);
    {
        dim3 grid(HW / QT, BB, 2);           // 240 x 4 x 2
        embed_kernel<<<grid, 128, embed_smem>>>(F_L, F_R);
    }
    {
        dim3 grid(HH, BB, 1);                // 512 blocks
        corr_kernel<<<grid, 256, corr_smem>>>(d0, out);
    }
}

// round 16
// speedup vs baseline: 1.3403x; 1.3403x over previous
#include <cuda_runtime.h>
#include <cuda_fp16.h>
#include <math.h>

#define BB 4
#define CC 128
#define HH 128
#define WW 240
#define EE 64
#define RNG 4
#define KK 9          // 2*RNG+1
#define HW (HH*WW)    // 30720
#define EPSN 1e-6f

// Normalized embeddings, fp16, [tensor][b][q][e], e contiguous. 31.5 MB.
__device__ __align__(16) __half g_emb[2][(size_t)BB * HW * EE];

// phi tf32 fragments: [kt(16)][nt(8)][lane(32)] -> uint4 (b0_hi,b1_hi,b0_lo,b1_lo).
__device__ uint4 g_phi_frag[16 * 8 * 32];

// ---------------------------------------------------------------------------
__device__ __forceinline__ void mma_tf32(float& d0, float& d1, float& d2, float& d3,
                                         unsigned a0, unsigned a1, unsigned a2, unsigned a3,
                                         unsigned b0, unsigned b1)
{
    asm volatile(
        "mma.sync.aligned.m16n8k8.row.col.f32.tf32.tf32.f32 "
        "{%0,%1,%2,%3}, {%4,%5,%6,%7}, {%8,%9}, {%0,%1,%2,%3};\n"
        : "+f"(d0), "+f"(d1), "+f"(d2), "+f"(d3)
        : "r"(a0), "r"(a1), "r"(a2), "r"(a3), "r"(b0), "r"(b1));
}

__device__ __forceinline__ unsigned cvt_tf32_rna(float x)
{
    unsigned r;
    asm("cvt.rna.tf32.f32 %0, %1;" : "=r"(r) : "f"(x));
    return r;
}

__device__ __forceinline__ unsigned round_tf32_bits(float x)
{
    unsigned u = __float_as_uint(x);
    return (u + 0x1000u) & 0xFFFFE000u;
}

__device__ __forceinline__ float2 h2f(unsigned u)
{
    __half2 h = *reinterpret_cast<__half2*>(&u);
    return __half22float2(h);
}

// ---- cp.async helpers -----------------------------------------------------
__device__ __forceinline__ void cp_async16(unsigned dst_smem, const void* src)
{
    asm volatile("cp.async.cg.shared.global [%0], [%1], 16;"
                 :: "r"(dst_smem), "l"(src));
}
__device__ __forceinline__ void cp_commit()
{
    asm volatile("cp.async.commit_group;");
}
template<int N>
__device__ __forceinline__ void cp_wait()
{
    asm volatile("cp.async.wait_group %0;" :: "n"(N));
}

// ---------------------------------------------------------------------------
// prep_phi: tf32 hi/lo B fragments.
// ---------------------------------------------------------------------------
__global__ void prep_phi_kernel(const float* __restrict__ phi)
{
    const int idx = blockIdx.x * blockDim.x + threadIdx.x;   // 0..4095
    if (idx >= 16 * 8 * 32) return;
    const int lane = idx & 31;
    const int nt   = (idx >> 5) & 7;
    const int kt   = idx >> 8;

    const int e  = nt * 8 + (lane >> 2);
    const int c0 = kt * 8 + (lane & 3);

    const float x0 = phi[e * CC + c0];
    const float x1 = phi[e * CC + c0 + 4];

    const unsigned h0 = cvt_tf32_rna(x0);
    const unsigned h1 = cvt_tf32_rna(x1);

    uint4 v;
    v.x = h0;
    v.y = h1;
    v.z = __float_as_uint(x0 - __uint_as_float(h0));
    v.w = __float_as_uint(x1 - __uint_as_float(h1));
    g_phi_frag[idx] = v;
}

// ---------------------------------------------------------------------------
// embed (round-11 best, unchanged): CH=32 double-buffer cp.async pipeline,
// tf32 MMA 2-product, coalesced fp16 epilogue via smem staging. 4 blocks/SM.
// ---------------------------------------------------------------------------
#define QT 128
#define S_A 136                   // floats per channel row (128 + 8 pad)
#define CH 32                     // channels per pipeline chunk
#define NCHUNK (CC / CH)          // 4
#define OS 72                     // output stage stride in halves

__global__ __launch_bounds__(128, 4)
void embed_kernel(const float* __restrict__ FL,
                  const float* __restrict__ FR)
{
    extern __shared__ __align__(16) float A_s[];   // [2][CH][S_A] = 34816 B

    const int t      = threadIdx.x;
    const int qbase  = blockIdx.x * QT;
    const int b      = blockIdx.y;
    const int tensor = blockIdx.z;

    const float* __restrict__ F =
        (tensor == 0 ? FL : FR) + (size_t)b * CC * HW;

    const int warp = t >> 5;
    const int lane = t & 31;
    const int g    = lane >> 2;
    const int tg   = lane & 3;

    const int tq_c = t & 31;
    #define ISSUE_CHUNK(ch, buf)                                              \
    {                                                                         \
        float* __restrict__ dstb = A_s + (buf) * (CH * S_A);                  \
        _Pragma("unroll")                                                     \
        for (int i = 0; i < 8; i++) {                                         \
            const int cl = i * 4 + warp;                                      \
            const float* src = &F[(size_t)((ch) * CH + cl) * HW + qbase + tq_c * 4]; \
            const unsigned dst = (unsigned)__cvta_generic_to_shared(          \
                &dstb[cl * S_A + tq_c * 4]);                                  \
            cp_async16(dst, src);                                             \
        }                                                                     \
        cp_commit();                                                          \
    }

    float acc[2][8][4];
#pragma unroll
    for (int mt = 0; mt < 2; mt++)
#pragma unroll
        for (int nt = 0; nt < 8; nt++)
#pragma unroll
            for (int i = 0; i < 4; i++) acc[mt][nt][i] = 0.0f;

    const uint4* __restrict__ Bf = g_phi_frag + lane;
    const int r0 = (warp * 2) * 16 + g;       // mt=0 output row (0..127)
    const int r2 = (warp * 2 + 1) * 16 + g;   // mt=1

    ISSUE_CHUNK(0, 0);

#pragma unroll
    for (int ch = 0; ch < NCHUNK; ch++) {
        if (ch + 1 < NCHUNK) {
            ISSUE_CHUNK(ch + 1, (ch + 1) & 1);
            cp_wait<1>();
        } else {
            cp_wait<0>();
        }
        __syncthreads();

        const float* __restrict__ buf = A_s + (ch & 1) * (CH * S_A);
#pragma unroll
        for (int ktl = 0; ktl < CH / 8; ktl++) {          // 4 k-tiles per chunk
            const int cl0 = ktl * 8 + tg;
            unsigned a[2][4];
            a[0][0] = round_tf32_bits(buf[cl0 * S_A + r0]);
            a[0][1] = round_tf32_bits(buf[cl0 * S_A + r0 + 8]);
            a[0][2] = round_tf32_bits(buf[(cl0 + 4) * S_A + r0]);
            a[0][3] = round_tf32_bits(buf[(cl0 + 4) * S_A + r0 + 8]);
            a[1][0] = round_tf32_bits(buf[cl0 * S_A + r2]);
            a[1][1] = round_tf32_bits(buf[cl0 * S_A + r2 + 8]);
            a[1][2] = round_tf32_bits(buf[(cl0 + 4) * S_A + r2]);
            a[1][3] = round_tf32_bits(buf[(cl0 + 4) * S_A + r2 + 8]);

            const int kt = ch * (CH / 8) + ktl;
#pragma unroll
            for (int nt = 0; nt < 8; nt++) {
                const uint4 bf = Bf[(kt * 8 + nt) * 32];
#pragma unroll
                for (int mt = 0; mt < 2; mt++) {
                    mma_tf32(acc[mt][nt][0], acc[mt][nt][1], acc[mt][nt][2], acc[mt][nt][3],
                             a[mt][0], a[mt][1], a[mt][2], a[mt][3], bf.x, bf.y);
                    mma_tf32(acc[mt][nt][0], acc[mt][nt][1], acc[mt][nt][2], acc[mt][nt][3],
                             a[mt][0], a[mt][1], a[mt][2], a[mt][3], bf.z, bf.w);
                }
            }
        }
        __syncthreads();
    }
    #undef ISSUE_CHUNK

    // ---- Normalize + stage to smem (reuse A_s; [QT][OS] halves = 18 KB) ----
    __half* __restrict__ stage = reinterpret_cast<__half*>(A_s);
#pragma unroll
    for (int mt = 0; mt < 2; mt++) {
        const int r = (mt == 0 ? r0 : r2);
        float s0 = 0.0f, s1 = 0.0f;
#pragma unroll
        for (int nt = 0; nt < 8; nt++) {
            s0 = fmaf(acc[mt][nt][0], acc[mt][nt][0], s0);
            s0 = fmaf(acc[mt][nt][1], acc[mt][nt][1], s0);
            s1 = fmaf(acc[mt][nt][2], acc[mt][nt][2], s1);
            s1 = fmaf(acc[mt][nt][3], acc[mt][nt][3], s1);
        }
        s0 += __shfl_xor_sync(0xffffffffu, s0, 1);
        s0 += __shfl_xor_sync(0xffffffffu, s0, 2);
        s1 += __shfl_xor_sync(0xffffffffu, s1, 1);
        s1 += __shfl_xor_sync(0xffffffffu, s1, 2);
        const float inv0 = 1.0f / (sqrtf(s0) + EPSN);
        const float inv1 = 1.0f / (sqrtf(s1) + EPSN);

#pragma unroll
        for (int nt = 0; nt < 8; nt++) {
            const int e = nt * 8 + 2 * tg;
            *reinterpret_cast<__half2*>(&stage[r * OS + e]) =
                __floats2half2_rn(acc[mt][nt][0] * inv0, acc[mt][nt][1] * inv0);
            *reinterpret_cast<__half2*>(&stage[(r + 8) * OS + e]) =
                __floats2half2_rn(acc[mt][nt][2] * inv1, acc[mt][nt][3] * inv1);
        }
    }
    __syncthreads();

    // ---- Copy stage -> global, fully coalesced (8 uint4/thread) ----
    __half* __restrict__ outT = g_emb[tensor] + ((size_t)b * HW + qbase) * EE;
#pragma unroll
    for (int i = 0; i < 8; i++) {
        const int idx = i * 128 + t;       // 0..1023
        const int row = idx >> 3;
        const int col = idx & 7;
        const uint4 v = *reinterpret_cast<const uint4*>(&stage[row * OS + col * 8]);
        reinterpret_cast<uint4*>(&outT[(size_t)row * EE])[col] = v;
    }
}

// ---------------------------------------------------------------------------
// corr: half-row blocks (grid z=2) with NARROWED 192-column FR stage.
// d0 in [0,64] => taps for half z reach cols [woff-68, woff+125]; window
// lo = z*48 covers both halves. fp16 stage, conflict-free uint4 layout
// (banks sub*4 mod 32, all distinct). 8-lane groups, shared-frac.
// ---------------------------------------------------------------------------
#define WHALF (WW / 2)      // 120
#define NSTG  192           // staged columns per block

__global__ __launch_bounds__(256)
void corr_kernel(const float* __restrict__ d0,
                 float* __restrict__ out)
{
    extern __shared__ __align__(16) char FRC_s[];   // 192*64 halves = 24576 B

    const int h    = blockIdx.x;
    const int b    = blockIdx.y;
    const int z    = blockIdx.z;
    const int woff = z * WHALF;
    const int lo   = z * (WW - NSTG);   // 0 or 48
    const int t    = threadIdx.x;

    const __half* __restrict__ fl_row =
        &g_emb[0][((size_t)b * HW + (size_t)h * WW) * EE];
    const __half* __restrict__ fr_row =
        &g_emb[1][((size_t)b * HW + (size_t)h * WW) * EE];
    const float* __restrict__ d_row = d0 + (size_t)b * HW + (size_t)h * WW;

    // Stage FR cols [lo, lo+192): 1536 uint4, 6 per thread.
    {
        const uint4* __restrict__ src =
            reinterpret_cast<const uint4*>(fr_row) + lo * 8;
        uint4* __restrict__ dst = reinterpret_cast<uint4*>(FRC_s);
#pragma unroll
        for (int i = 0; i < 6; i++) {
            const int idx = i * 256 + t;
            dst[idx] = __ldg(src + idx);
        }
    }
    __syncthreads();

    const int gid = t >> 3;        // 32 groups of 8 lanes
    const int sub = t & 7;
    const uint4* __restrict__ FR4 = reinterpret_cast<const uint4*>(FRC_s);

#pragma unroll 1
    for (int it = 0; it < 4; it++) {
        const int wl = gid + 32 * it;          // 0..127 within half
        const bool active = (wl < WHALF);
        const int w = woff + (active ? wl : (WHALF - 1));

        const uint4 flv =
            __ldg(reinterpret_cast<const uint4*>(&fl_row[(size_t)w * EE]) + sub);
        const float2 fl0 = h2f(flv.x);
        const float2 fl1 = h2f(flv.y);
        const float2 fl2 = h2f(flv.z);
        const float2 fl3 = h2f(flv.w);

        const float d = __ldg(&d_row[w]);
        const float xf   = (float)w - d;
        const float f0f  = floorf(xf);
        const float frac = xf - f0f;
        const int base   = (int)f0f - RNG;

        float s[10];
#pragma unroll
        for (int j = 0; j < 10; j++) {
            const int idx = min(max(base + j, 0), WW - 1) - lo;   // 0..191
            const uint4 frv = FR4[idx * 8 + sub];
            const float2 a0 = h2f(frv.x);
            const float2 a1 = h2f(frv.y);
            const float2 a2 = h2f(frv.z);
            const float2 a3 = h2f(frv.w);
            float dot;
            dot = fl0.x * a0.x;
            dot = fmaf(fl0.y, a0.y, dot);
            dot = fmaf(fl1.x, a1.x, dot);
            dot = fmaf(fl1.y, a1.y, dot);
            dot = fmaf(fl2.x, a2.x, dot);
            dot = fmaf(fl2.y, a2.y, dot);
            dot = fmaf(fl3.x, a3.x, dot);
            dot = fmaf(fl3.y, a3.y, dot);
            s[j] = dot;
        }

#pragma unroll
        for (int j = 0; j < 10; j++) {
            float p = s[j];
            p += __shfl_xor_sync(0xffffffffu, p, 4);
            p += __shfl_xor_sync(0xffffffffu, p, 2);
            p += __shfl_xor_sync(0xffffffffu, p, 1);
            s[j] = p;
        }

        float sA = s[8], sB = s[9];
#pragma unroll
        for (int k = 1; k < 8; k++)
            if (sub == k) { sA = s[8 - k]; sB = s[9 - k]; }

        if (active) {
            const float omf = 1.0f - frac;
            out[(((size_t)b * KK + sub) * HH + h) * WW + w] = sA * omf + sB * frac;
            if (sub == 0)
                out[(((size_t)b * KK + 8) * HH + h) * WW + w] = s[0] * omf + s[1] * frac;
        }
    }
}

extern "C" void kernel_launch(void* const* d_in, const int* in_sizes, int n_in,
                              void* d_out, int out_size)
{
    const float* F_L   = (const float*)d_in[0];
    const float* F_R   = (const float*)d_in[1];
    const float* d0    = (const float*)d_in[2];
    const float* phi_w = (const float*)d_in[3];
    float* out = (float*)d_out;

    const int embed_smem = 2 * CH * S_A * (int)sizeof(float);   // 34816 B
    const int corr_smem  = NSTG * EE * (int)sizeof(__half);     // 24576 B
    cudaFuncSetAttribute(embed_kernel,
                         cudaFuncAttributeMaxDynamicSharedMemorySize, embed_smem);
    cudaFuncSetAttribute(corr_kernel,
                         cudaFuncAttributeMaxDynamicSharedMemorySize, corr_smem);

    prep_phi_kernel<<<16, 256>>>(phi_w);
    {
        dim3 grid(HW / QT, BB, 2);           // 240 x 4 x 2
        embed_kernel<<<grid, 128, embed_smem>>>(F_L, F_R);
    }
    {
        dim3 grid(HH, BB, 2);                // 1024 blocks
        corr_kernel<<<grid, 256, corr_smem>>>(d0, out);
    }
}

// round 17
// speedup vs baseline: 1.4370x; 1.0721x over previous
#include <cuda_runtime.h>
#include <cuda_fp16.h>
#include <math.h>

#define BB 4
#define CC 128
#define HH 128
#define WW 240
#define EE 64
#define RNG 4
#define KK 9          // 2*RNG+1
#define HW (HH*WW)    // 30720
#define EPSN 1e-6f

// Normalized embeddings, fp16, [tensor][b][q][e], e contiguous. 31.5 MB.
__device__ __align__(16) __half g_emb[2][(size_t)BB * HW * EE];

// phi bf16 fragments for m16n8k16: [kt(8)][nt(8)][lane(32)] -> uint4
// (b0_hi, b1_hi, b0_lo, b1_lo). 32 KB, L1-resident.
__device__ uint4 g_phi_frag[8 * 8 * 32];

// ---------------------------------------------------------------------------
// mma.sync m16n8k16 row.col f32.bf16.bf16.f32
// ---------------------------------------------------------------------------
__device__ __forceinline__ void mma_bf16(float& d0, float& d1, float& d2, float& d3,
                                         unsigned a0, unsigned a1, unsigned a2, unsigned a3,
                                         unsigned b0, unsigned b1)
{
    asm volatile(
        "mma.sync.aligned.m16n8k16.row.col.f32.bf16.bf16.f32 "
        "{%0,%1,%2,%3}, {%4,%5,%6,%7}, {%8,%9}, {%0,%1,%2,%3};\n"
        : "+f"(d0), "+f"(d1), "+f"(d2), "+f"(d3)
        : "r"(a0), "r"(a1), "r"(a2), "r"(a3), "r"(b0), "r"(b1));
}

// Pack two fp32 into bf16x2: result.lo = bf16(lo), result.hi = bf16(hi).
__device__ __forceinline__ unsigned cvt_bf16x2(float hi, float lo)
{
    unsigned d;
    asm("cvt.rn.bf16x2.f32 %0, %1, %2;" : "=r"(d) : "f"(hi), "f"(lo));
    return d;
}

// Residual pack: given hi-pack h for (x_lo, x_hi), return bf16x2 of residues.
__device__ __forceinline__ unsigned bf16x2_resid(unsigned h, float x_lo, float x_hi)
{
    const float f_lo = __uint_as_float(h << 16);
    const float f_hi = __uint_as_float(h & 0xffff0000u);
    return cvt_bf16x2(x_hi - f_hi, x_lo - f_lo);
}

__device__ __forceinline__ float2 h2f(unsigned u)
{
    __half2 h = *reinterpret_cast<__half2*>(&u);
    return __half22float2(h);
}

// ---- cp.async helpers -----------------------------------------------------
__device__ __forceinline__ void cp_async16(unsigned dst_smem, const void* src)
{
    asm volatile("cp.async.cg.shared.global [%0], [%1], 16;"
                 :: "r"(dst_smem), "l"(src));
}
__device__ __forceinline__ void cp_commit()
{
    asm volatile("cp.async.commit_group;");
}
template<int N>
__device__ __forceinline__ void cp_wait()
{
    asm volatile("cp.async.wait_group %0;" :: "n"(N));
}

// ---------------------------------------------------------------------------
// prep_phi: bf16 hi/lo B fragments for m16n8k16.col.
// B[k=c][n=e] = phi[e][c]; thread tg covers k = 2t,2t+1 (b0) and 2t+8,2t+9 (b1).
// ---------------------------------------------------------------------------
__global__ void prep_phi_kernel(const float* __restrict__ phi)
{
    const int idx = blockIdx.x * blockDim.x + threadIdx.x;   // 0..2047
    if (idx >= 8 * 8 * 32) return;
    const int lane = idx & 31;
    const int nt   = (idx >> 5) & 7;
    const int kt   = idx >> 8;                               // 0..7

    const int e  = nt * 8 + (lane >> 2);
    const int c0 = kt * 16 + 2 * (lane & 3);

    const float x0 = phi[e * CC + c0];
    const float x1 = phi[e * CC + c0 + 1];
    const float x2 = phi[e * CC + c0 + 8];
    const float x3 = phi[e * CC + c0 + 9];

    uint4 v;
    v.x = cvt_bf16x2(x1, x0);              // b0_hi
    v.y = cvt_bf16x2(x3, x2);              // b1_hi
    v.z = bf16x2_resid(v.x, x0, x1);       // b0_lo
    v.w = bf16x2_resid(v.y, x2, x3);       // b1_lo
    g_phi_frag[idx] = v;
}

// ---------------------------------------------------------------------------
// embed: CH=32 double-buffer cp.async pipeline; m16n8k16 bf16 3-product MMA
// (halves B-table + A-LDS L1tex work vs k8-tf32). Producer permutes k-columns
// so consumer frag loads land at rows {t,t+4,t+8,t+12} (bank 8*tg+g: conflict-
// free). Coalesced fp16 epilogue via smem staging. 4 blocks/SM.
// ---------------------------------------------------------------------------
#define QT 128
#define S_A 136                   // floats per channel row (128 + 8 pad)
#define CH 32                     // channels per pipeline chunk
#define NCHUNK (CC / CH)          // 4
#define OS 72                     // output stage stride in halves

__global__ __launch_bounds__(128, 4)
void embed_kernel(const float* __restrict__ FL,
                  const float* __restrict__ FR)
{
    extern __shared__ __align__(16) float A_s[];   // [2][CH][S_A] = 34816 B

    const int t      = threadIdx.x;
    const int qbase  = blockIdx.x * QT;
    const int b      = blockIdx.y;
    const int tensor = blockIdx.z;

    const float* __restrict__ F =
        (tensor == 0 ? FL : FR) + (size_t)b * CC * HW;

    const int warp = t >> 5;
    const int lane = t & 31;
    const int g    = lane >> 2;
    const int tg   = lane & 3;

    // Producer: channel cl -> permuted smem row so that consumer reads
    // k = {2tg, 2tg+1, 2tg+8, 2tg+9} at rows {tg, tg+4, tg+8, tg+12}.
    const int tq_c = t & 31;
    #define ISSUE_CHUNK(ch, buf)                                              \
    {                                                                         \
        float* __restrict__ dstb = A_s + (buf) * (CH * S_A);                  \
        _Pragma("unroll")                                                     \
        for (int i = 0; i < 8; i++) {                                         \
            const int cl  = i * 4 + warp;                                     \
            const int kl  = cl & 15;                                          \
            const int grp = cl >> 4;                                          \
            const int r16 = (kl < 8) ? ((kl >> 1) + (kl & 1) * 4)             \
                                     : (8 + ((kl - 8) >> 1) + ((kl - 8) & 1) * 4); \
            const int row = grp * 16 + r16;                                   \
            const float* src = &F[(size_t)((ch) * CH + cl) * HW + qbase + tq_c * 4]; \
            const unsigned dst = (unsigned)__cvta_generic_to_shared(          \
                &dstb[row * S_A + tq_c * 4]);                                 \
            cp_async16(dst, src);                                             \
        }                                                                     \
        cp_commit();                                                          \
    }

    float acc[2][8][4];
#pragma unroll
    for (int mt = 0; mt < 2; mt++)
#pragma unroll
        for (int nt = 0; nt < 8; nt++)
#pragma unroll
            for (int i = 0; i < 4; i++) acc[mt][nt][i] = 0.0f;

    const uint4* __restrict__ Bf = g_phi_frag + lane;
    const int r0 = (warp * 2) * 16 + g;       // mt=0 output row (0..127)
    const int r2 = (warp * 2 + 1) * 16 + g;   // mt=1

    ISSUE_CHUNK(0, 0);

#pragma unroll
    for (int ch = 0; ch < NCHUNK; ch++) {
        if (ch + 1 < NCHUNK) {
            ISSUE_CHUNK(ch + 1, (ch + 1) & 1);
            cp_wait<1>();
        } else {
            cp_wait<0>();
        }
        __syncthreads();

        const float* __restrict__ buf = A_s + (ch & 1) * (CH * S_A);
#pragma unroll
        for (int ktl = 0; ktl < 2; ktl++) {            // 2 k16-tiles per chunk
            const int rb = ktl * 16;

            // A-split: 8 LDS.32 + bf16 hi/lo pack per m-tile.
            unsigned ah[2][4], al[2][4];
#pragma unroll
            for (int mt = 0; mt < 2; mt++) {
                const int r = (mt == 0 ? r0 : r2);
                const float e0 = buf[(rb + tg)      * S_A + r];      // k=2tg,   row r
                const float e1 = buf[(rb + tg + 4)  * S_A + r];      // k=2tg+1, row r
                const float e2 = buf[(rb + tg)      * S_A + r + 8];
                const float e3 = buf[(rb + tg + 4)  * S_A + r + 8];
                const float e4 = buf[(rb + tg + 8)  * S_A + r];      // k=2tg+8, row r
                const float e5 = buf[(rb + tg + 12) * S_A + r];      // k=2tg+9
                const float e6 = buf[(rb + tg + 8)  * S_A + r + 8];
                const float e7 = buf[(rb + tg + 12) * S_A + r + 8];

                ah[mt][0] = cvt_bf16x2(e1, e0);
                ah[mt][1] = cvt_bf16x2(e3, e2);
                ah[mt][2] = cvt_bf16x2(e5, e4);
                ah[mt][3] = cvt_bf16x2(e7, e6);
                al[mt][0] = bf16x2_resid(ah[mt][0], e0, e1);
                al[mt][1] = bf16x2_resid(ah[mt][1], e2, e3);
                al[mt][2] = bf16x2_resid(ah[mt][2], e4, e5);
                al[mt][3] = bf16x2_resid(ah[mt][3], e6, e7);
            }

            const int kt = ch * 2 + ktl;               // global k16-tile 0..7
#pragma unroll
            for (int nt = 0; nt < 8; nt++) {
                const uint4 bf = Bf[(kt * 8 + nt) * 32];
#pragma unroll
                for (int mt = 0; mt < 2; mt++) {
                    mma_bf16(acc[mt][nt][0], acc[mt][nt][1], acc[mt][nt][2], acc[mt][nt][3],
                             ah[mt][0], ah[mt][1], ah[mt][2], ah[mt][3], bf.x, bf.y); // hi*hi
                    mma_bf16(acc[mt][nt][0], acc[mt][nt][1], acc[mt][nt][2], acc[mt][nt][3],
                             ah[mt][0], ah[mt][1], ah[mt][2], ah[mt][3], bf.z, bf.w); // hi*lo
                    mma_bf16(acc[mt][nt][0], acc[mt][nt][1], acc[mt][nt][2], acc[mt][nt][3],
                             al[mt][0], al[mt][1], al[mt][2], al[mt][3], bf.x, bf.y); // lo*hi
                }
            }
        }
        __syncthreads();
    }
    #undef ISSUE_CHUNK

    // ---- Normalize + stage to smem (reuse A_s; [QT][OS] halves = 18 KB) ----
    __half* __restrict__ stage = reinterpret_cast<__half*>(A_s);
#pragma unroll
    for (int mt = 0; mt < 2; mt++) {
        const int r = (mt == 0 ? r0 : r2);
        float s0 = 0.0f, s1 = 0.0f;
#pragma unroll
        for (int nt = 0; nt < 8; nt++) {
            s0 = fmaf(acc[mt][nt][0], acc[mt][nt][0], s0);
            s0 = fmaf(acc[mt][nt][1], acc[mt][nt][1], s0);
            s1 = fmaf(acc[mt][nt][2], acc[mt][nt][2], s1);
            s1 = fmaf(acc[mt][nt][3], acc[mt][nt][3], s1);
        }
        s0 += __shfl_xor_sync(0xffffffffu, s0, 1);
        s0 += __shfl_xor_sync(0xffffffffu, s0, 2);
        s1 += __shfl_xor_sync(0xffffffffu, s1, 1);
        s1 += __shfl_xor_sync(0xffffffffu, s1, 2);
        const float inv0 = 1.0f / (sqrtf(s0) + EPSN);
        const float inv1 = 1.0f / (sqrtf(s1) + EPSN);

#pragma unroll
        for (int nt = 0; nt < 8; nt++) {
            const int e = nt * 8 + 2 * tg;
            *reinterpret_cast<__half2*>(&stage[r * OS + e]) =
                __floats2half2_rn(acc[mt][nt][0] * inv0, acc[mt][nt][1] * inv0);
            *reinterpret_cast<__half2*>(&stage[(r + 8) * OS + e]) =
                __floats2half2_rn(acc[mt][nt][2] * inv1, acc[mt][nt][3] * inv1);
        }
    }
    __syncthreads();

    // ---- Copy stage -> global, fully coalesced (8 uint4/thread) ----
    __half* __restrict__ outT = g_emb[tensor] + ((size_t)b * HW + qbase) * EE;
#pragma unroll
    for (int i = 0; i < 8; i++) {
        const int idx = i * 128 + t;       // 0..1023
        const int row = idx >> 3;
        const int col = idx & 7;
        const uint4 v = *reinterpret_cast<const uint4*>(&stage[row * OS + col * 8]);
        reinterpret_cast<uint4*>(&outT[(size_t)row * EE])[col] = v;
    }
}

// ---------------------------------------------------------------------------
// corr (round-11 best, unchanged): fp16 embeddings; 8-lane groups;
// FR row staged in smem (30 KB, conflict-free). Shared-frac factorization.
// ---------------------------------------------------------------------------
__global__ __launch_bounds__(256)
void corr_kernel(const float* __restrict__ d0,
                 float* __restrict__ out)
{
    extern __shared__ __align__(16) char FRC_s[];   // 240*64 halves = 30720 B

    const int h = blockIdx.x;
    const int b = blockIdx.y;
    const int t = threadIdx.x;

    const __half* __restrict__ fl_row =
        &g_emb[0][((size_t)b * HW + (size_t)h * WW) * EE];
    const __half* __restrict__ fr_row =
        &g_emb[1][((size_t)b * HW + (size_t)h * WW) * EE];
    const float* __restrict__ d_row = d0 + (size_t)b * HW + (size_t)h * WW;

    {
        const uint4* __restrict__ src = reinterpret_cast<const uint4*>(fr_row);
        uint4* __restrict__ dst = reinterpret_cast<uint4*>(FRC_s);
#pragma unroll
        for (int i = 0; i < 8; i++) {
            const int idx = i * 256 + t;
            if (idx < 1920) dst[idx] = __ldg(src + idx);
        }
    }
    __syncthreads();

    const int gid = t >> 3;        // 32 groups of 8 lanes
    const int sub = t & 7;
    const uint4* __restrict__ FR4 = reinterpret_cast<const uint4*>(FRC_s);

#pragma unroll 1
    for (int it = 0; it < 8; it++) {
        const int w = gid + 32 * it;
        const bool active = (w < WW);
        const int wc = active ? w : (WW - 1);

        const uint4 flv =
            __ldg(reinterpret_cast<const uint4*>(&fl_row[(size_t)wc * EE]) + sub);
        const float2 fl0 = h2f(flv.x);
        const float2 fl1 = h2f(flv.y);
        const float2 fl2 = h2f(flv.z);
        const float2 fl3 = h2f(flv.w);

        const float d = __ldg(&d_row[wc]);
        const float xf   = (float)wc - d;
        const float f0f  = floorf(xf);
        const float frac = xf - f0f;
        const int base   = (int)f0f - RNG;

        float s[10];
#pragma unroll
        for (int j = 0; j < 10; j++) {
            const int idx = min(max(base + j, 0), WW - 1);
            const uint4 frv = FR4[idx * 8 + sub];
            const float2 a0 = h2f(frv.x);
            const float2 a1 = h2f(frv.y);
            const float2 a2 = h2f(frv.z);
            const float2 a3 = h2f(frv.w);
            float dot;
            dot = fl0.x * a0.x;
            dot = fmaf(fl0.y, a0.y, dot);
            dot = fmaf(fl1.x, a1.x, dot);
            dot = fmaf(fl1.y, a1.y, dot);
            dot = fmaf(fl2.x, a2.x, dot);
            dot = fmaf(fl2.y, a2.y, dot);
            dot = fmaf(fl3.x, a3.x, dot);
            dot = fmaf(fl3.y, a3.y, dot);
            s[j] = dot;
        }

#pragma unroll
        for (int j = 0; j < 10; j++) {
            float p = s[j];
            p += __shfl_xor_sync(0xffffffffu, p, 4);
            p += __shfl_xor_sync(0xffffffffu, p, 2);
            p += __shfl_xor_sync(0xffffffffu, p, 1);
            s[j] = p;
        }

        float sA = s[8], sB = s[9];
#pragma unroll
        for (int k = 1; k < 8; k++)
            if (sub == k) { sA = s[8 - k]; sB = s[9 - k]; }

        if (active) {
            const float omf = 1.0f - frac;
            out[(((size_t)b * KK + sub) * HH + h) * WW + w] = sA * omf + sB * frac;
            if (sub == 0)
                out[(((size_t)b * KK + 8) * HH + h) * WW + w] = s[0] * omf + s[1] * frac;
        }
    }
}

extern "C" void kernel_launch(void* const* d_in, const int* in_sizes, int n_in,
                              void* d_out, int out_size)
{
    const float* F_L   = (const float*)d_in[0];
    const float* F_R   = (const float*)d_in[1];
    const float* d0    = (const float*)d_in[2];
    const float* phi_w = (const float*)d_in[3];
    float* out = (float*)d_out;

    const int embed_smem = 2 * CH * S_A * (int)sizeof(float);   // 34816 B
    const int corr_smem  = WW * EE * (int)sizeof(__half);       // 30720 B
    cudaFuncSetAttribute(embed_kernel,
                         cudaFuncAttributeMaxDynamicSharedMemorySize, embed_smem);
    cudaFuncSetAttribute(corr_kernel,
                         cudaFuncAttributeMaxDynamicSharedMemorySize, corr_smem);

    prep_phi_kernel<<<8, 256>>>(phi_w);
    {
        dim3 grid(HW / QT, BB, 2);           // 240 x 4 x 2
        embed_kernel<<<grid, 128, embed_smem>>>(F_L, F_R);
    }
    {
        dim3 grid(HH, BB, 1);                // 512 blocks
        corr_kernel<<<grid, 256, corr_smem>>>(d0, out);
    }
}